// round 4
// baseline (speedup 1.0000x reference)
#include <cuda_runtime.h>
#include <cstdint>

// ---------------------------------------------------------------------------
// Attention_layer: N=B*H*W=32768 tiny attention problems, fused, fp32 with
// packed f32x2 FMA (Blackwell FFMA2 path). One warp per position, one CTA per
// (b, h, 8-wide w tile) for coalesced gmem access.
// ---------------------------------------------------------------------------

#define ULL unsigned long long

__device__ __forceinline__ ULL d2(float x) {
    ULL r; asm("mov.b64 %0,{%1,%1};" : "=l"(r) : "f"(x)); return r;
}
__device__ __forceinline__ void fma2(ULL& a, ULL b, ULL c) {
    asm("fma.rn.f32x2 %0,%1,%2,%0;" : "+l"(a) : "l"(b), "l"(c));
}
__device__ __forceinline__ void add2(ULL& a, ULL b) {
    asm("add.rn.f32x2 %0,%1,%0;" : "+l"(a) : "l"(b));
}
__device__ __forceinline__ float2 unpk(ULL a) {
    float lo, hi; asm("mov.b64 {%0,%1},%2;" : "=f"(lo), "=f"(hi) : "l"(a));
    return make_float2(lo, hi);
}
__device__ __forceinline__ float ex2(float x) {
    float r; asm("ex2.approx.f32 %0,%1;" : "=f"(r) : "f"(x)); return r;
}

// Problem constants
static constexpr int B  = 8;
static constexpr int CH = 64;
static constexpr int D  = 32;
static constexpr int H  = 64;
static constexpr int W  = 64;
static constexpr int S  = 32;           // shrink = CH/2
static constexpr int WT = 8;            // w-tile per CTA (= warps per CTA)
static constexpr int HW = H * W;        // 4096

// smem layout (floats)
static constexpr int XSTRIDE  = CH * D + 4;          // 2052, pad for conflict-free transpose store
static constexpr int OFF_X    = 0;                    // WT * 2052 = 16416
static constexpr int OFF_WKT  = OFF_X + WT * XSTRIDE; // 16416
static constexpr int OFF_WQT  = OFF_WKT + CH * S;     // 18464
static constexpr int OFF_WVT  = OFF_WQT + CH * S;     // 20512
static constexpr int OFF_WOT  = OFF_WVT + CH * S;     // 22560  [s][c] layout, 32*64
static constexpr int OFF_BK   = OFF_WOT + S * CH;     // 24608
static constexpr int OFF_BQ   = OFF_BK + S;
static constexpr int OFF_BV   = OFF_BQ + S;
static constexpr int OFF_BO   = OFF_BV + S;           // 24704 (64)
static constexpr int OFF_SCR  = OFF_BO + CH;          // 24768
static constexpr int RP       = 36;                   // padded row (32 + 4)
static constexpr int SCR_PW   = 3 * 32 * RP;          // 3456 floats per warp
static constexpr int OFF_OUT  = OFF_SCR + WT * SCR_PW;// 52416
static constexpr int SMEM_FLOATS = OFF_OUT + CH * WT; // 52928
static constexpr size_t SMEM_BYTES = (size_t)SMEM_FLOATS * 4; // 211712 B

__global__ __launch_bounds__(256, 1)
void attn_fused_kernel(const float* __restrict__ x,
                       const float* __restrict__ Wk, const float* __restrict__ bk,
                       const float* __restrict__ Wq, const float* __restrict__ bq,
                       const float* __restrict__ Wv, const float* __restrict__ bv,
                       const float* __restrict__ Wo, const float* __restrict__ bo,
                       const float* __restrict__ factor,
                       float* __restrict__ out)
{
    extern __shared__ float sm[];
    const int tid  = threadIdx.x;
    const int blk  = blockIdx.x;
    const int b    = blk >> 9;          // 512 blocks per batch (64 h * 8 wtiles)
    const int rem  = blk & 511;
    const int h    = rem >> 3;
    const int w0   = (rem & 7) << 3;

    // ---- Stage weights (transposed) ----
    for (int i = tid; i < CH * S; i += 256) {
        int c = i >> 5, s = i & 31;
        sm[OFF_WKT + i] = Wk[s * CH + c];
        sm[OFF_WQT + i] = Wq[s * CH + c];
        sm[OFF_WVT + i] = Wv[s * CH + c];
        int s2 = i >> 6, c2 = i & 63;
        sm[OFF_WOT + i] = Wo[c2 * S + s2];
    }
    if (tid < S) {
        sm[OFF_BK + tid] = bk[tid];
        sm[OFF_BQ + tid] = bq[tid];
        sm[OFF_BV + tid] = bv[tid];
    }
    if (tid < CH) sm[OFF_BO + tid] = bo[tid];

    // ---- Stage x tile: [c][d][w0..w0+7] gmem -> smem [w][c*32+d] ----
    const float* base_in = x + (size_t)b * (CH * D) * HW + h * W + w0;
    for (int it = 0; it < 32; ++it) {
        int idx = it * 256 + tid;       // 0..8191
        int cd  = idx >> 2;             // 0..2047
        int w2  = (idx & 3) << 1;       // 0,2,4,6
        float2 v = *(const float2*)(base_in + (size_t)cd * HW + w2);
        sm[OFF_X + w2 * XSTRIDE + cd]       = v.x;
        sm[OFF_X + (w2 + 1) * XSTRIDE + cd] = v.y;
    }
    __syncthreads();

    const int warp = tid >> 5;
    const int lane = tid & 31;
    const int sg   = lane >> 3;  // 0..3
    const int jg   = lane & 7;   // 0..7

    float* xw   = sm + OFF_X + warp * XSTRIDE;
    float* bufA = sm + OFF_SCR + warp * SCR_PW;   // kT, later a
    float* bufQ = bufA + 32 * RP;                 // qT, later om
    float* bufV = bufQ + 32 * RP;                 // vT

    // ================= Phase A: projections k,q,v ==========================
    // accum[sp][td] packs (row 2sp, row 2sp+1) of this lane's s-block sg*8..+7
    // over its d-block jg*4..+3
    ULL ak[4][4], aq[4][4], av[4][4];
    {
        const ULL* bk2 = (const ULL*)(sm + OFF_BK);
        const ULL* bq2 = (const ULL*)(sm + OFF_BQ);
        const ULL* bv2 = (const ULL*)(sm + OFF_BV);
        #pragma unroll
        for (int sp = 0; sp < 4; ++sp) {
            ULL bK = bk2[sg * 4 + sp], bQ = bq2[sg * 4 + sp], bV = bv2[sg * 4 + sp];
            #pragma unroll
            for (int td = 0; td < 4; ++td) { ak[sp][td] = bK; aq[sp][td] = bQ; av[sp][td] = bV; }
        }
    }
    #pragma unroll 4
    for (int c = 0; c < CH; ++c) {
        float4 xv = *(const float4*)(xw + c * 32 + jg * 4);
        ULL xd0 = d2(xv.x), xd1 = d2(xv.y), xd2 = d2(xv.z), xd3 = d2(xv.w);
        const ulonglong2* wkp = (const ulonglong2*)(sm + OFF_WKT + c * 32 + sg * 8);
        const ulonglong2* wqp = (const ulonglong2*)(sm + OFF_WQT + c * 32 + sg * 8);
        const ulonglong2* wvp = (const ulonglong2*)(sm + OFF_WVT + c * 32 + sg * 8);
        ulonglong2 wka = wkp[0], wkb = wkp[1];
        ulonglong2 wqa = wqp[0], wqb = wqp[1];
        ulonglong2 wva = wvp[0], wvb = wvp[1];
        ULL xd[4] = {xd0, xd1, xd2, xd3};
        #pragma unroll
        for (int td = 0; td < 4; ++td) {
            fma2(ak[0][td], wka.x, xd[td]); fma2(ak[1][td], wka.y, xd[td]);
            fma2(ak[2][td], wkb.x, xd[td]); fma2(ak[3][td], wkb.y, xd[td]);
            fma2(aq[0][td], wqa.x, xd[td]); fma2(aq[1][td], wqa.y, xd[td]);
            fma2(aq[2][td], wqb.x, xd[td]); fma2(aq[3][td], wqb.y, xd[td]);
            fma2(av[0][td], wva.x, xd[td]); fma2(av[1][td], wva.y, xd[td]);
            fma2(av[2][td], wvb.x, xd[td]); fma2(av[3][td], wvb.y, xd[td]);
        }
    }
    // Store transposed: kT/qT/vT [d][s], rows padded to RP
    #pragma unroll
    for (int td = 0; td < 4; ++td) {
        int d = jg * 4 + td;
        ULL* kT = (ULL*)(bufA + d * RP + sg * 8);
        ULL* qT = (ULL*)(bufQ + d * RP + sg * 8);
        ULL* vT = (ULL*)(bufV + d * RP + sg * 8);
        #pragma unroll
        for (int sp = 0; sp < 4; ++sp) { kT[sp] = ak[sp][td]; qT[sp] = aq[sp][td]; vT[sp] = av[sp][td]; }
    }
    __syncwarp();

    // ================= Phase B: scores[i][j] = sum_s k[s][i] q[s][j] =======
    // lane tile: i in {sg + 4*ti}, j in {jg + 8*tj}  (strided -> conflict-free)
    ULL acc[8][4];
    #pragma unroll
    for (int ti = 0; ti < 8; ++ti)
        #pragma unroll
        for (int tj = 0; tj < 4; ++tj) acc[ti][tj] = 0ull;

    #pragma unroll 2
    for (int sq = 0; sq < 8; ++sq) {
        ulonglong2 kk[8];
        #pragma unroll
        for (int ti = 0; ti < 8; ++ti)
            kk[ti] = *(const ulonglong2*)(bufA + (4 * ti + sg) * RP + sq * 4);
        ulonglong2 qq[4];
        #pragma unroll
        for (int tj = 0; tj < 4; ++tj)
            qq[tj] = *(const ulonglong2*)(bufQ + (8 * tj + jg) * RP + sq * 4);
        #pragma unroll
        for (int ti = 0; ti < 8; ++ti)
            #pragma unroll
            for (int tj = 0; tj < 4; ++tj) {
                fma2(acc[ti][tj], kk[ti].x, qq[tj].x);
                fma2(acc[ti][tj], kk[ti].y, qq[tj].y);
            }
    }
    float sc[8][4];
    #pragma unroll
    for (int ti = 0; ti < 8; ++ti)
        #pragma unroll
        for (int tj = 0; tj < 4; ++tj) { float2 u = unpk(acc[ti][tj]); sc[ti][tj] = u.x + u.y; }

    // ================= Phase C: softmax over i (per column j) ==============
    // scale 1/sqrt(S) folded into exp2 coefficient
    const float CEXP = 0.17677669529663687f * 1.44269504088896340f;
    #pragma unroll
    for (int tj = 0; tj < 4; ++tj) {
        float m = sc[0][tj];
        #pragma unroll
        for (int ti = 1; ti < 8; ++ti) m = fmaxf(m, sc[ti][tj]);
        m = fmaxf(m, __shfl_xor_sync(0xffffffffu, m, 8));
        m = fmaxf(m, __shfl_xor_sync(0xffffffffu, m, 16));
        float sum = 0.f;
        #pragma unroll
        for (int ti = 0; ti < 8; ++ti) {
            float e = ex2((sc[ti][tj] - m) * CEXP);
            sc[ti][tj] = e; sum += e;
        }
        sum += __shfl_xor_sync(0xffffffffu, sum, 8);
        sum += __shfl_xor_sync(0xffffffffu, sum, 16);
        float r = 1.0f / sum;
        #pragma unroll
        for (int ti = 0; ti < 8; ++ti) sc[ti][tj] *= r;
    }
    // store a[i][j] into bufA (k dead)
    #pragma unroll
    for (int ti = 0; ti < 8; ++ti) {
        int i = 4 * ti + sg;
        #pragma unroll
        for (int tj = 0; tj < 4; ++tj) bufA[i * RP + 8 * tj + jg] = sc[ti][tj];
    }
    __syncwarp();

    // ================= Phase D: o[s][j] = sum_d v[s][d] a[d][j] ============
    ULL ao[4][4];
    #pragma unroll
    for (int sp = 0; sp < 4; ++sp)
        #pragma unroll
        for (int tj = 0; tj < 4; ++tj) ao[sp][tj] = 0ull;

    #pragma unroll 4
    for (int d = 0; d < D; ++d) {
        const ulonglong2* vp = (const ulonglong2*)(bufV + d * RP + sg * 8);
        ulonglong2 va = vp[0], vb = vp[1];
        ULL ad[4];
        #pragma unroll
        for (int tj = 0; tj < 4; ++tj) ad[tj] = d2(bufA[d * RP + 8 * tj + jg]);
        #pragma unroll
        for (int tj = 0; tj < 4; ++tj) {
            fma2(ao[0][tj], va.x, ad[tj]); fma2(ao[1][tj], va.y, ad[tj]);
            fma2(ao[2][tj], vb.x, ad[tj]); fma2(ao[3][tj], vb.y, ad[tj]);
        }
    }

    // ================= Phase E: om[s] = mean_j o[s][j] =====================
    #pragma unroll
    for (int sp = 0; sp < 4; ++sp) {
        ULL s2 = ao[sp][0];
        add2(s2, ao[sp][1]); add2(s2, ao[sp][2]); add2(s2, ao[sp][3]);
        float2 u = unpk(s2);
        float o0 = u.x, o1 = u.y;
        o0 += __shfl_xor_sync(0xffffffffu, o0, 1);
        o0 += __shfl_xor_sync(0xffffffffu, o0, 2);
        o0 += __shfl_xor_sync(0xffffffffu, o0, 4);
        o1 += __shfl_xor_sync(0xffffffffu, o1, 1);
        o1 += __shfl_xor_sync(0xffffffffu, o1, 2);
        o1 += __shfl_xor_sync(0xffffffffu, o1, 4);
        if (jg == 0) {
            bufQ[sg * 8 + 2 * sp]     = o0 * (1.0f / 32.0f);
            bufQ[sg * 8 + 2 * sp + 1] = o1 * (1.0f / 32.0f);
        }
    }
    __syncwarp();

    // ================= Phase F: mean_d x + output conv =====================
    const float fact = factor[0];
    float mx0 = 0.f, mx1 = 0.f;
    #pragma unroll 4
    for (int t = 0; t < 32; ++t) {
        int dd = (lane + t) & 31;                 // rotated: conflict-free
        mx0 += xw[lane * 32 + dd];
        mx1 += xw[(lane + 32) * 32 + dd];
    }
    float ac0 = 0.f, ac1 = 0.f;
    #pragma unroll 4
    for (int s = 0; s < S; ++s) {
        float om = bufQ[s];
        ac0 += sm[OFF_WOT + s * CH + lane]      * om;
        ac1 += sm[OFF_WOT + s * CH + lane + 32] * om;
    }
    float r0 = mx0 * (1.0f / 32.0f) + fact * (ac0 + sm[OFF_BO + lane]);
    float r1 = mx1 * (1.0f / 32.0f) + fact * (ac1 + sm[OFF_BO + lane + 32]);
    sm[OFF_OUT + lane * 8 + warp]        = r0;
    sm[OFF_OUT + (lane + 32) * 8 + warp] = r1;

    __syncthreads();
    // coalesced output: out[b][c][h][w0..w0+7]
    for (int e = tid; e < CH * WT; e += 256) {
        int c = e >> 3, wl = e & 7;
        out[(((size_t)b * CH + c) * H + h) * W + w0 + wl] = sm[OFF_OUT + e];
    }
}

extern "C" void kernel_launch(void* const* d_in, const int* in_sizes, int n_in,
                              void* d_out, int out_size)
{
    (void)in_sizes; (void)n_in; (void)out_size;
    const float* x      = (const float*)d_in[0];
    const float* Wk     = (const float*)d_in[1];
    const float* bk     = (const float*)d_in[2];
    const float* Wq     = (const float*)d_in[3];
    const float* bq     = (const float*)d_in[4];
    const float* Wv     = (const float*)d_in[5];
    const float* bv     = (const float*)d_in[6];
    const float* Wo     = (const float*)d_in[7];
    const float* bo     = (const float*)d_in[8];
    const float* factor = (const float*)d_in[9];
    float* out = (float*)d_out;

    cudaFuncSetAttribute(attn_fused_kernel,
                         cudaFuncAttributeMaxDynamicSharedMemorySize,
                         (int)SMEM_BYTES);
    dim3 grid(B * H * (W / WT));   // 4096
    dim3 block(256);
    attn_fused_kernel<<<grid, block, SMEM_BYTES>>>(
        x, Wk, bk, Wq, bq, Wv, bv, Wo, bo, factor, out);
}